// round 8
// baseline (speedup 1.0000x reference)
#include <cuda_runtime.h>
#include <cuda_bf16.h>
#include <cstdint>

// Problem constants
#define Bsz 2
#define Ssz 2048
#define Esz 1024
#define Hsz 16
#define HDd 64
#define Msz (Bsz * Ssz)      // 4096
#define NQKV (3 * Esz)       // 3072

// bf16 hi/lo pre-split operands for the dense GEMMs
__device__ __nv_bfloat16 sXh[Msz * Esz], sXl[Msz * Esz];            // [m][k]
__device__ __nv_bfloat16 sWqh[NQKV * Esz], sWql[NQKV * Esz];        // [n][k]
__device__ __nv_bfloat16 sWph[Esz * Esz], sWpl[Esz * Esz];          // [n][k]
__device__ __nv_bfloat16 sOh[Msz * Esz], sOl[Msz * Esz];            // [m][k] merged heads

// bf16 hi/lo head-split Q/K/V: [B*H][S][64] (Q pre-scaled by 0.125)
__device__ __nv_bfloat16 bQh[Bsz * Hsz * Ssz * HDd], bQl[Bsz * Hsz * Ssz * HDd];
__device__ __nv_bfloat16 bKh[Bsz * Hsz * Ssz * HDd], bKl[Bsz * Hsz * Ssz * HDd];
__device__ __nv_bfloat16 bVh[Bsz * Hsz * Ssz * HDd], bVl[Bsz * Hsz * Ssz * HDd];

// ---------------------------------------------------------------------------
// helpers
// ---------------------------------------------------------------------------
__device__ __forceinline__ void split2(float x0, float x1, uint32_t& hi, uint32_t& lo) {
    __nv_bfloat162 h = __floats2bfloat162_rn(x0, x1);
    float r0 = x0 - __bfloat162float(__low2bfloat16(h));
    float r1 = x1 - __bfloat162float(__high2bfloat16(h));
    __nv_bfloat162 l = __floats2bfloat162_rn(r0, r1);
    hi = *(uint32_t*)&h;
    lo = *(uint32_t*)&l;
}

__device__ __forceinline__ void mma16(float* d, const uint32_t* a, const uint32_t* b) {
    asm volatile(
        "mma.sync.aligned.m16n8k16.row.col.f32.bf16.bf16.f32 "
        "{%0,%1,%2,%3}, {%4,%5,%6,%7}, {%8,%9}, {%0,%1,%2,%3};"
        : "+f"(d[0]), "+f"(d[1]), "+f"(d[2]), "+f"(d[3])
        : "r"(a[0]), "r"(a[1]), "r"(a[2]), "r"(a[3]), "r"(b[0]), "r"(b[1]));
}

__device__ __forceinline__ void ldm4(uint32_t* r, uint32_t addr) {
    asm volatile("ldmatrix.sync.aligned.m8n8.x4.shared.b16 {%0,%1,%2,%3}, [%4];"
                 : "=r"(r[0]), "=r"(r[1]), "=r"(r[2]), "=r"(r[3]) : "r"(addr));
}

__device__ __forceinline__ void ldm4t(uint32_t* r, uint32_t addr) {
    asm volatile("ldmatrix.sync.aligned.m8n8.x4.trans.shared.b16 {%0,%1,%2,%3}, [%4];"
                 : "=r"(r[0]), "=r"(r[1]), "=r"(r[2]), "=r"(r[3]) : "r"(addr));
}

__device__ __forceinline__ void cp16(uint32_t dst, const void* src) {
    asm volatile("cp.async.cg.shared.global [%0], [%1], 16;"
                 :: "r"(dst), "l"(src));
}
#define CP_COMMIT() asm volatile("cp.async.commit_group;" ::: "memory")
#define CP_WAIT(n)  asm volatile("cp.async.wait_group %0;" :: "n"(n) : "memory")

__device__ __forceinline__ uint32_t smem_u32(const void* p) {
    uint32_t a;
    asm("{ .reg .u64 t; cvta.to.shared.u64 t, %1; cvt.u32.u64 %0, t; }"
        : "=r"(a) : "l"(p));
    return a;
}

// ---------------------------------------------------------------------------
// Dense GEMM machinery: CTA 128x128, BK=32, 256 threads, pitch-80 smem,
// cp.async double buffer (single sync per stage), ldmatrix, bf16x3.
// ---------------------------------------------------------------------------
#define TILE_B 10240            // 128 * 80
#define STAGE_B (4 * TILE_B)    // 40960
#define SMEM_DYN (2 * STAGE_B)  // 81920

__device__ __forceinline__ void load_stage(
    uint32_t sbst, const __nv_bfloat16* Ah, const __nv_bfloat16* Al,
    const __nv_bfloat16* Bh, const __nv_bfloat16* Bl,
    int m0, int n0, int k0, int tid) {
#pragma unroll
    for (int g = 0; g < 2; g++) {
        const int idx = g * 256 + tid;
        const int row = idx >> 2, ch = idx & 3;
        const uint32_t d = sbst + row * 80 + ch * 16;
        const int aoff = (m0 + row) * Esz + k0 + ch * 8;
        const int boff = (n0 + row) * Esz + k0 + ch * 8;
        cp16(d, Ah + aoff);
        cp16(d + TILE_B, Al + aoff);
        cp16(d + 2 * TILE_B, Bh + boff);
        cp16(d + 3 * TILE_B, Bl + boff);
    }
}

__device__ __forceinline__ void mma_stage(float acc[4][4][4], uint32_t sbst,
                                          int wm0, int wn0, int lane) {
    const int laneRowA = ((lane >> 3) & 1) * 8 + (lane & 7);
    const int chA = lane >> 4;
    const int laneRowB = (lane >> 4) * 8 + (lane & 7);
    const int chB = (lane >> 3) & 1;
#pragma unroll
    for (int ks = 0; ks < 2; ks++) {
        uint32_t ah[4][4], al[4][4], bh[2][4], bl[2][4];
#pragma unroll
        for (int i = 0; i < 4; i++) {
            const uint32_t ra =
                sbst + (wm0 + i * 16 + laneRowA) * 80 + (ks * 2 + chA) * 16;
            ldm4(ah[i], ra);
            ldm4(al[i], ra + TILE_B);
        }
#pragma unroll
        for (int jp = 0; jp < 2; jp++) {
            const uint32_t rb = sbst + 2 * TILE_B +
                (wn0 + jp * 16 + laneRowB) * 80 + (ks * 2 + chB) * 16;
            ldm4(bh[jp], rb);
            ldm4(bl[jp], rb + TILE_B);
        }
#pragma unroll
        for (int i = 0; i < 4; i++)
#pragma unroll
            for (int j = 0; j < 4; j++) {
                const uint32_t* BH_ = &bh[j >> 1][(j & 1) * 2];
                const uint32_t* BL_ = &bl[j >> 1][(j & 1) * 2];
                mma16(acc[i][j], ah[i], BH_);
                mma16(acc[i][j], ah[i], BL_);
                mma16(acc[i][j], al[i], BH_);
            }
    }
}

#define GEMM_MAINLOOP(Ah, Al, Bh, Bl)                                        \
    extern __shared__ char dsm[];                                            \
    const uint32_t sb = smem_u32(dsm);                                       \
    const int tid = threadIdx.x;                                             \
    const int wid = tid >> 5, lane = tid & 31;                               \
    const int wm0 = (wid >> 2) * 64, wn0 = (wid & 3) * 32;                   \
    const int m0 = blockIdx.y * 128, n0 = blockIdx.x * 128;                  \
    float acc[4][4][4];                                                      \
    _Pragma("unroll") for (int i = 0; i < 4; i++)                            \
        _Pragma("unroll") for (int j = 0; j < 4; j++)                        \
            _Pragma("unroll") for (int r = 0; r < 4; r++) acc[i][j][r] = 0.f;\
    load_stage(sb, Ah, Al, Bh, Bl, m0, n0, 0, tid);                          \
    CP_COMMIT();                                                             \
    for (int s = 0; s < Esz / 32; s++) {                                     \
        CP_WAIT(0);                                                          \
        __syncthreads();                                                     \
        if (s + 1 < Esz / 32) {                                              \
            load_stage(sb + ((s + 1) & 1) * STAGE_B, Ah, Al, Bh, Bl,         \
                       m0, n0, (s + 1) * 32, tid);                           \
            CP_COMMIT();                                                     \
        }                                                                    \
        mma_stage(acc, sb + (s & 1) * STAGE_B, wm0, wn0, lane);              \
    }

// ---------------------------------------------------------------------------
// Kernel 1: qkv GEMM; epilogue writes pre-split bf16 Q/K/V (Q scaled 0.125)
// ---------------------------------------------------------------------------
__global__ __launch_bounds__(256, 2) void gemm_qkv(const float* __restrict__ bias) {
    GEMM_MAINLOOP(sXh, sXl, sWqh, sWql)

    const int g2 = lane >> 2, t2 = lane & 3;
#pragma unroll
    for (int i = 0; i < 4; i++) {
#pragma unroll
        for (int j = 0; j < 4; j++) {
            const int r0 = m0 + wm0 + i * 16 + g2;
            const int c0 = n0 + wn0 + j * 8 + t2 * 2;
            const int part = c0 >> 10, e = c0 & 1023;
            const int hh = e >> 6, d = e & 63;
            __nv_bfloat16 *dh, *dl;
            if (part == 0)      { dh = bQh; dl = bQl; }
            else if (part == 1) { dh = bKh; dl = bKl; }
            else                { dh = bVh; dl = bVl; }
            const float sc = (part == 0) ? 0.125f : 1.f;
            const float bb0 = bias[c0], bb1 = bias[c0 + 1];
            {
                const int b = r0 >> 11, sq = r0 & 2047;
                const int off = (((b << 4) + hh) * Ssz + sq) * HDd + d;
                uint32_t hi, lo;
                split2((acc[i][j][0] + bb0) * sc, (acc[i][j][1] + bb1) * sc, hi, lo);
                *(uint32_t*)(dh + off) = hi;
                *(uint32_t*)(dl + off) = lo;
            }
            {
                const int r1 = r0 + 8;
                const int b = r1 >> 11, sq = r1 & 2047;
                const int off = (((b << 4) + hh) * Ssz + sq) * HDd + d;
                uint32_t hi, lo;
                split2((acc[i][j][2] + bb0) * sc, (acc[i][j][3] + bb1) * sc, hi, lo);
                *(uint32_t*)(dh + off) = hi;
                *(uint32_t*)(dl + off) = lo;
            }
        }
    }
}

// ---------------------------------------------------------------------------
// Kernel 3: proj GEMM -> d_out
// ---------------------------------------------------------------------------
__global__ __launch_bounds__(256, 2) void gemm_proj(const float* __restrict__ bias,
                                                    float* __restrict__ out) {
    GEMM_MAINLOOP(sOh, sOl, sWph, sWpl)

    const int g2 = lane >> 2, t2 = lane & 3;
#pragma unroll
    for (int i = 0; i < 4; i++) {
#pragma unroll
        for (int j = 0; j < 4; j++) {
            const int r0 = m0 + wm0 + i * 16 + g2;
            const int c0 = n0 + wn0 + j * 8 + t2 * 2;
            const float b0 = bias[c0], b1 = bias[c0 + 1];
            float2 v0 = make_float2(acc[i][j][0] + b0, acc[i][j][1] + b1);
            float2 v1 = make_float2(acc[i][j][2] + b0, acc[i][j][3] + b1);
            *(float2*)(out + r0 * Esz + c0) = v0;
            *(float2*)(out + (r0 + 8) * Esz + c0) = v1;
        }
    }
}

// ---------------------------------------------------------------------------
// Pre-split kernels (X, weights)
// ---------------------------------------------------------------------------
__global__ __launch_bounds__(256) void split_plain(const float4* __restrict__ src,
                                                   uint2* __restrict__ h2,
                                                   uint2* __restrict__ l2) {
    const int i = blockIdx.x * 256 + threadIdx.x;
    const float4 v = src[i];
    uint32_t h0, l0, h1, l1;
    split2(v.x, v.y, h0, l0);
    split2(v.z, v.w, h1, l1);
    h2[i] = make_uint2(h0, h1);
    l2[i] = make_uint2(l0, l1);
}

__global__ __launch_bounds__(256) void split_w_tr(const float* __restrict__ W,
                                                  __nv_bfloat16* __restrict__ Th,
                                                  __nv_bfloat16* __restrict__ Tl,
                                                  int N) {
    __shared__ float t[32][33];
    const int k0 = blockIdx.y * 32, n0 = blockIdx.x * 32;
    const int tx = threadIdx.x & 31, ty = threadIdx.x >> 5;
#pragma unroll
    for (int r = ty; r < 32; r += 8)
        t[r][tx] = W[(k0 + r) * N + n0 + tx];
    __syncthreads();
#pragma unroll
    for (int r = ty; r < 32; r += 8) {
        const float v = t[tx][r];
        __nv_bfloat16 h = __float2bfloat16_rn(v);
        __nv_bfloat16 l = __float2bfloat16_rn(v - __bfloat162float(h));
        Th[(n0 + r) * Esz + k0 + tx] = h;
        Tl[(n0 + r) * Esz + k0 + tx] = l;
    }
}

// ---------------------------------------------------------------------------
// Kernel 2: tensor-core causal flash attention.
// grid = (16 q-tiles of 128 rows, 32 bh), 128 threads = 4 warps.
// Warp w owns q rows w*32 .. w*32+31 (two m16 fragments).
// kv tiles of 64, double buffered, single sync per tile.
// smem: Q hi/lo (128 rows) + 2 stages x (Kh,Kl,Vh,Vl), pitch 144B rows.
// ---------------------------------------------------------------------------
#define AT_PITCH 144
#define AT_TILE (64 * AT_PITCH)              // 9216
#define AT_Q (4 * AT_TILE)                   // Q hi/lo 128 rows = 36864
#define AT_STAGE_B (4 * AT_TILE)             // 36864
#define AT_SMEM (AT_Q + 2 * AT_STAGE_B)      // 110592

__device__ __forceinline__ void at_load_kv(uint32_t st, int base, int kv0, int tid) {
#pragma unroll
    for (int gq = 0; gq < 4; gq++) {
        const int idx = gq * 128 + tid;          // 0..511
        const int row = idx >> 3, ch = idx & 7;
        const uint32_t d = st + row * AT_PITCH + ch * 16;
        const int off = base + (kv0 + row) * HDd + ch * 8;
        cp16(d, bKh + off);
        cp16(d + AT_TILE, bKl + off);
        cp16(d + 2 * AT_TILE, bVh + off);
        cp16(d + 3 * AT_TILE, bVl + off);
    }
}

__global__ __launch_bounds__(128, 2) void attn_tc() {
    extern __shared__ char dsm[];
    const uint32_t sb = smem_u32(dsm);
    const int tid = threadIdx.x, wid = tid >> 5, lane = tid & 31;
    const int bh = blockIdx.y;
    const int q0 = (gridDim.x - 1 - blockIdx.x) * 128;  // heavy tiles first
    const int wq0 = wid * 32;
    const int g = lane >> 2, t = lane & 3;
    const int base = bh * Ssz * HDd;

    // Q tile hi/lo (128 rows)
#pragma unroll
    for (int gq = 0; gq < 8; gq++) {
        const int idx = gq * 128 + tid;
        const int row = idx >> 3, ch = idx & 7;
        const uint32_t d = sb + row * AT_PITCH + ch * 16;
        const int off = base + (q0 + row) * HDd + ch * 8;
        cp16(d, bQh + off);
        cp16(d + 2 * AT_TILE, bQl + off);
    }
    at_load_kv(sb + AT_Q, base, 0, tid);
    CP_COMMIT();

    const int T = q0 / 64 + 2;

    float oacc[2][8][4];
#pragma unroll
    for (int mf = 0; mf < 2; mf++)
#pragma unroll
        for (int j = 0; j < 8; j++)
#pragma unroll
            for (int r = 0; r < 4; r++) oacc[mf][j][r] = 0.f;
    float m_a[2] = {-1e30f, -1e30f}, m_b[2] = {-1e30f, -1e30f};
    float l_a[2] = {0.f, 0.f}, l_b[2] = {0.f, 0.f};
    uint32_t qh[2][4][4], ql[2][4][4];

    const int laneRowB = (lane >> 4) * 8 + (lane & 7);
    const int chB = (lane >> 3) & 1;

    for (int tt = 0; tt < T; tt++) {
        CP_WAIT(0);
        __syncthreads();
        if (tt + 1 < T) {
            at_load_kv(sb + AT_Q + ((tt + 1) & 1) * AT_STAGE_B,
                       base, (tt + 1) * 64, tid);
            CP_COMMIT();
        }

        if (tt == 0) {
#pragma unroll
            for (int mf = 0; mf < 2; mf++)
#pragma unroll
                for (int ks = 0; ks < 4; ks++) {
                    const uint32_t ra = sb +
                        (wq0 + mf * 16 + (lane & 15)) * AT_PITCH +
                        (ks * 2 + (lane >> 4)) * 16;
                    ldm4(qh[mf][ks], ra);
                    ldm4(ql[mf][ks], ra + 2 * AT_TILE);
                }
        }

        const uint32_t st = sb + AT_Q + (tt & 1) * AT_STAGE_B;

        // S = Q K^T (bf16x3), two m-frags per warp
        float sacc[2][8][4];
#pragma unroll
        for (int mf = 0; mf < 2; mf++)
#pragma unroll
            for (int j = 0; j < 8; j++)
#pragma unroll
                for (int r = 0; r < 4; r++) sacc[mf][j][r] = 0.f;

#pragma unroll
        for (int jp = 0; jp < 4; jp++) {
#pragma unroll
            for (int ks = 0; ks < 4; ks++) {
                const uint32_t rb = st + (jp * 16 + laneRowB) * AT_PITCH +
                                    (ks * 2 + chB) * 16;
                uint32_t kh4[4], kl4[4];
                ldm4(kh4, rb);
                ldm4(kl4, rb + AT_TILE);
#pragma unroll
                for (int mf = 0; mf < 2; mf++) {
                    mma16(sacc[mf][jp * 2], qh[mf][ks], &kh4[0]);
                    mma16(sacc[mf][jp * 2], qh[mf][ks], &kl4[0]);
                    mma16(sacc[mf][jp * 2], ql[mf][ks], &kh4[0]);
                    mma16(sacc[mf][jp * 2 + 1], qh[mf][ks], &kh4[2]);
                    mma16(sacc[mf][jp * 2 + 1], qh[mf][ks], &kl4[2]);
                    mma16(sacc[mf][jp * 2 + 1], ql[mf][ks], &kh4[2]);
                }
            }
        }

        // causal mask (last two kv tiles can cross the diagonal)
        if (tt >= T - 2) {
            const int kvb = tt * 64;
#pragma unroll
            for (int mf = 0; mf < 2; mf++) {
                const int rowa = q0 + wq0 + mf * 16 + g;
                const int rowb = rowa + 8;
#pragma unroll
                for (int j = 0; j < 8; j++) {
                    const int c0 = kvb + j * 8 + t * 2;
                    if (c0 > rowa) sacc[mf][j][0] = -1e30f;
                    if (c0 + 1 > rowa) sacc[mf][j][1] = -1e30f;
                    if (c0 > rowb) sacc[mf][j][2] = -1e30f;
                    if (c0 + 1 > rowb) sacc[mf][j][3] = -1e30f;
                }
            }
        }

        // online softmax per m-frag
        uint32_t ph[2][4][4], pl[2][4][4];
#pragma unroll
        for (int mf = 0; mf < 2; mf++) {
            float mxa = -1e30f, mxb = -1e30f;
#pragma unroll
            for (int j = 0; j < 8; j++) {
                mxa = fmaxf(mxa, fmaxf(sacc[mf][j][0], sacc[mf][j][1]));
                mxb = fmaxf(mxb, fmaxf(sacc[mf][j][2], sacc[mf][j][3]));
            }
            mxa = fmaxf(mxa, __shfl_xor_sync(0xffffffffu, mxa, 1));
            mxa = fmaxf(mxa, __shfl_xor_sync(0xffffffffu, mxa, 2));
            mxb = fmaxf(mxb, __shfl_xor_sync(0xffffffffu, mxb, 1));
            mxb = fmaxf(mxb, __shfl_xor_sync(0xffffffffu, mxb, 2));
            const float mna = fmaxf(m_a[mf], mxa), mnb = fmaxf(m_b[mf], mxb);
            const float ca = __expf(m_a[mf] - mna), cb = __expf(m_b[mf] - mnb);
            m_a[mf] = mna;
            m_b[mf] = mnb;

            float ra = 0.f, rb = 0.f;
#pragma unroll
            for (int j = 0; j < 8; j++) {
                const float p0 = __expf(sacc[mf][j][0] - mna);
                const float p1 = __expf(sacc[mf][j][1] - mna);
                const float p2 = __expf(sacc[mf][j][2] - mnb);
                const float p3 = __expf(sacc[mf][j][3] - mnb);
                ra += p0 + p1;
                rb += p2 + p3;
                uint32_t h01, l01, h23, l23;
                split2(p0, p1, h01, l01);
                split2(p2, p3, h23, l23);
                const int ks = j >> 1, half = (j & 1) * 2;
                ph[mf][ks][half] = h01;
                ph[mf][ks][half + 1] = h23;
                pl[mf][ks][half] = l01;
                pl[mf][ks][half + 1] = l23;
            }
            ra += __shfl_xor_sync(0xffffffffu, ra, 1);
            ra += __shfl_xor_sync(0xffffffffu, ra, 2);
            rb += __shfl_xor_sync(0xffffffffu, rb, 1);
            rb += __shfl_xor_sync(0xffffffffu, rb, 2);
            l_a[mf] = l_a[mf] * ca + ra;
            l_b[mf] = l_b[mf] * cb + rb;

#pragma unroll
            for (int j = 0; j < 8; j++) {
                oacc[mf][j][0] *= ca;
                oacc[mf][j][1] *= ca;
                oacc[mf][j][2] *= cb;
                oacc[mf][j][3] *= cb;
            }
        }

        // O += P V (bf16x3), V via trans-ldmatrix
        const uint32_t vbase = st + 2 * AT_TILE;
#pragma unroll
        for (int ks = 0; ks < 4; ks++) {
#pragma unroll
            for (int jp = 0; jp < 4; jp++) {
                const uint32_t va = vbase + (ks * 16 + (lane & 15)) * AT_PITCH +
                                    (jp * 16 + (lane >> 4) * 8) * 2;
                uint32_t vh4[4], vl4[4];
                ldm4t(vh4, va);
                ldm4t(vl4, va + AT_TILE);
#pragma unroll
                for (int mf = 0; mf < 2; mf++) {
                    mma16(oacc[mf][jp * 2], ph[mf][ks], &vh4[0]);
                    mma16(oacc[mf][jp * 2], ph[mf][ks], &vl4[0]);
                    mma16(oacc[mf][jp * 2], pl[mf][ks], &vh4[0]);
                    mma16(oacc[mf][jp * 2 + 1], ph[mf][ks], &vh4[2]);
                    mma16(oacc[mf][jp * 2 + 1], ph[mf][ks], &vl4[2]);
                    mma16(oacc[mf][jp * 2 + 1], pl[mf][ks], &vh4[2]);
                }
            }
        }
    }

    // normalize + write merged-head pre-split output
    const int b = bh >> 4, h = bh & 15;
#pragma unroll
    for (int mf = 0; mf < 2; mf++) {
        const float ia = 1.f / l_a[mf], ib = 1.f / l_b[mf];
        const int rowa = q0 + wq0 + mf * 16 + g;
        const int moa = (b * Ssz + rowa) * Esz + h * HDd;
        const int mob = (b * Ssz + rowa + 8) * Esz + h * HDd;
#pragma unroll
        for (int j = 0; j < 8; j++) {
            const int d = j * 8 + t * 2;
            uint32_t h01, l01, h23, l23;
            split2(oacc[mf][j][0] * ia, oacc[mf][j][1] * ia, h01, l01);
            split2(oacc[mf][j][2] * ib, oacc[mf][j][3] * ib, h23, l23);
            *(uint32_t*)(sOh + moa + d) = h01;
            *(uint32_t*)(sOl + moa + d) = l01;
            *(uint32_t*)(sOh + mob + d) = h23;
            *(uint32_t*)(sOl + mob + d) = l23;
        }
    }
}

// ---------------------------------------------------------------------------
extern "C" void kernel_launch(void* const* d_in, const int* in_sizes, int n_in,
                              void* d_out, int out_size) {
    const float* x = (const float*)d_in[0];
    const float* w_qkv = (const float*)d_in[1];
    const float* b_qkv = (const float*)d_in[2];
    const float* w_proj = (const float*)d_in[3];
    const float* b_proj = (const float*)d_in[4];
    float* out = (float*)d_out;

    static bool attr_done = false;
    if (!attr_done) {
        cudaFuncSetAttribute(gemm_qkv, cudaFuncAttributeMaxDynamicSharedMemorySize, SMEM_DYN);
        cudaFuncSetAttribute(gemm_proj, cudaFuncAttributeMaxDynamicSharedMemorySize, SMEM_DYN);
        cudaFuncSetAttribute(attn_tc, cudaFuncAttributeMaxDynamicSharedMemorySize, AT_SMEM);
        attr_done = true;
    }

    __nv_bfloat16 *pXh, *pXl, *pWqh, *pWql, *pWph, *pWpl;
    cudaGetSymbolAddress((void**)&pXh, sXh);
    cudaGetSymbolAddress((void**)&pXl, sXl);
    cudaGetSymbolAddress((void**)&pWqh, sWqh);
    cudaGetSymbolAddress((void**)&pWql, sWql);
    cudaGetSymbolAddress((void**)&pWph, sWph);
    cudaGetSymbolAddress((void**)&pWpl, sWpl);

    split_plain<<<Msz * Esz / 4 / 256, 256>>>((const float4*)x, (uint2*)pXh, (uint2*)pXl);
    split_w_tr<<<dim3(NQKV / 32, Esz / 32), 256>>>(w_qkv, pWqh, pWql, NQKV);
    split_w_tr<<<dim3(Esz / 32, Esz / 32), 256>>>(w_proj, pWph, pWpl, Esz);
    gemm_qkv<<<dim3(NQKV / 128, Msz / 128), 256, SMEM_DYN>>>(b_qkv);
    attn_tc<<<dim3(Ssz / 128, Bsz * Hsz), 128, AT_SMEM>>>();
    gemm_proj<<<dim3(Esz / 128, Msz / 128), 256, SMEM_DYN>>>(b_proj, out);
}

// round 9
// speedup vs baseline: 1.0371x; 1.0371x over previous
#include <cuda_runtime.h>
#include <cuda_bf16.h>
#include <cstdint>

// Problem constants
#define Bsz 2
#define Ssz 2048
#define Esz 1024
#define Hsz 16
#define HDd 64
#define Msz (Bsz * Ssz)      // 4096
#define NQKV (3 * Esz)       // 3072

// bf16 hi/lo pre-split operands for the dense GEMMs
__device__ __nv_bfloat16 sXh[Msz * Esz], sXl[Msz * Esz];            // [m][k]
__device__ __nv_bfloat16 sWqh[NQKV * Esz], sWql[NQKV * Esz];        // [n][k]
__device__ __nv_bfloat16 sWph[Esz * Esz], sWpl[Esz * Esz];          // [n][k]
__device__ __nv_bfloat16 sOh[Msz * Esz], sOl[Msz * Esz];            // [m][k] merged heads

// bf16 hi/lo head-split Q/K/V: [B*H][S][64] (Q pre-scaled by 0.125)
__device__ __nv_bfloat16 bQh[Bsz * Hsz * Ssz * HDd], bQl[Bsz * Hsz * Ssz * HDd];
__device__ __nv_bfloat16 bKh[Bsz * Hsz * Ssz * HDd], bKl[Bsz * Hsz * Ssz * HDd];
__device__ __nv_bfloat16 bVh[Bsz * Hsz * Ssz * HDd], bVl[Bsz * Hsz * Ssz * HDd];

// ---------------------------------------------------------------------------
// helpers
// ---------------------------------------------------------------------------
__device__ __forceinline__ void split2(float x0, float x1, uint32_t& hi, uint32_t& lo) {
    __nv_bfloat162 h = __floats2bfloat162_rn(x0, x1);
    float r0 = x0 - __bfloat162float(__low2bfloat16(h));
    float r1 = x1 - __bfloat162float(__high2bfloat16(h));
    __nv_bfloat162 l = __floats2bfloat162_rn(r0, r1);
    hi = *(uint32_t*)&h;
    lo = *(uint32_t*)&l;
}

__device__ __forceinline__ void mma16(float* d, const uint32_t* a, const uint32_t* b) {
    asm volatile(
        "mma.sync.aligned.m16n8k16.row.col.f32.bf16.bf16.f32 "
        "{%0,%1,%2,%3}, {%4,%5,%6,%7}, {%8,%9}, {%0,%1,%2,%3};"
        : "+f"(d[0]), "+f"(d[1]), "+f"(d[2]), "+f"(d[3])
        : "r"(a[0]), "r"(a[1]), "r"(a[2]), "r"(a[3]), "r"(b[0]), "r"(b[1]));
}

__device__ __forceinline__ void ldm4(uint32_t* r, uint32_t addr) {
    asm volatile("ldmatrix.sync.aligned.m8n8.x4.shared.b16 {%0,%1,%2,%3}, [%4];"
                 : "=r"(r[0]), "=r"(r[1]), "=r"(r[2]), "=r"(r[3]) : "r"(addr));
}

__device__ __forceinline__ void ldm4t(uint32_t* r, uint32_t addr) {
    asm volatile("ldmatrix.sync.aligned.m8n8.x4.trans.shared.b16 {%0,%1,%2,%3}, [%4];"
                 : "=r"(r[0]), "=r"(r[1]), "=r"(r[2]), "=r"(r[3]) : "r"(addr));
}

__device__ __forceinline__ void cp16(uint32_t dst, const void* src) {
    asm volatile("cp.async.cg.shared.global [%0], [%1], 16;"
                 :: "r"(dst), "l"(src));
}
#define CP_COMMIT() asm volatile("cp.async.commit_group;" ::: "memory")
#define CP_WAIT(n)  asm volatile("cp.async.wait_group %0;" :: "n"(n) : "memory")

__device__ __forceinline__ uint32_t smem_u32(const void* p) {
    uint32_t a;
    asm("{ .reg .u64 t; cvta.to.shared.u64 t, %1; cvt.u32.u64 %0, t; }"
        : "=r"(a) : "l"(p));
    return a;
}

// ---------------------------------------------------------------------------
// Dense GEMM machinery: CTA 128x128, BK=32, 256 threads, pitch-80 smem,
// cp.async double buffer (single sync per stage), ldmatrix, bf16x3.
// ---------------------------------------------------------------------------
#define TILE_B 10240            // 128 * 80
#define STAGE_B (4 * TILE_B)    // 40960
#define SMEM_DYN (2 * STAGE_B)  // 81920

__device__ __forceinline__ void load_stage(
    uint32_t sbst, const __nv_bfloat16* Ah, const __nv_bfloat16* Al,
    const __nv_bfloat16* Bh, const __nv_bfloat16* Bl,
    int m0, int n0, int k0, int tid) {
#pragma unroll
    for (int g = 0; g < 2; g++) {
        const int idx = g * 256 + tid;
        const int row = idx >> 2, ch = idx & 3;
        const uint32_t d = sbst + row * 80 + ch * 16;
        const int aoff = (m0 + row) * Esz + k0 + ch * 8;
        const int boff = (n0 + row) * Esz + k0 + ch * 8;
        cp16(d, Ah + aoff);
        cp16(d + TILE_B, Al + aoff);
        cp16(d + 2 * TILE_B, Bh + boff);
        cp16(d + 3 * TILE_B, Bl + boff);
    }
}

__device__ __forceinline__ void mma_stage(float acc[4][4][4], uint32_t sbst,
                                          int wm0, int wn0, int lane) {
    const int laneRowA = ((lane >> 3) & 1) * 8 + (lane & 7);
    const int chA = lane >> 4;
    const int laneRowB = (lane >> 4) * 8 + (lane & 7);
    const int chB = (lane >> 3) & 1;
#pragma unroll
    for (int ks = 0; ks < 2; ks++) {
        uint32_t ah[4][4], al[4][4], bh[2][4], bl[2][4];
#pragma unroll
        for (int i = 0; i < 4; i++) {
            const uint32_t ra =
                sbst + (wm0 + i * 16 + laneRowA) * 80 + (ks * 2 + chA) * 16;
            ldm4(ah[i], ra);
            ldm4(al[i], ra + TILE_B);
        }
#pragma unroll
        for (int jp = 0; jp < 2; jp++) {
            const uint32_t rb = sbst + 2 * TILE_B +
                (wn0 + jp * 16 + laneRowB) * 80 + (ks * 2 + chB) * 16;
            ldm4(bh[jp], rb);
            ldm4(bl[jp], rb + TILE_B);
        }
#pragma unroll
        for (int i = 0; i < 4; i++)
#pragma unroll
            for (int j = 0; j < 4; j++) {
                const uint32_t* BH_ = &bh[j >> 1][(j & 1) * 2];
                const uint32_t* BL_ = &bl[j >> 1][(j & 1) * 2];
                mma16(acc[i][j], ah[i], BH_);
                mma16(acc[i][j], ah[i], BL_);
                mma16(acc[i][j], al[i], BH_);
            }
    }
}

#define GEMM_MAINLOOP(Ah, Al, Bh, Bl)                                        \
    extern __shared__ char dsm[];                                            \
    const uint32_t sb = smem_u32(dsm);                                       \
    const int tid = threadIdx.x;                                             \
    const int wid = tid >> 5, lane = tid & 31;                               \
    const int wm0 = (wid >> 2) * 64, wn0 = (wid & 3) * 32;                   \
    const int m0 = blockIdx.y * 128, n0 = blockIdx.x * 128;                  \
    float acc[4][4][4];                                                      \
    _Pragma("unroll") for (int i = 0; i < 4; i++)                            \
        _Pragma("unroll") for (int j = 0; j < 4; j++)                        \
            _Pragma("unroll") for (int r = 0; r < 4; r++) acc[i][j][r] = 0.f;\
    load_stage(sb, Ah, Al, Bh, Bl, m0, n0, 0, tid);                          \
    CP_COMMIT();                                                             \
    for (int s = 0; s < Esz / 32; s++) {                                     \
        CP_WAIT(0);                                                          \
        __syncthreads();                                                     \
        if (s + 1 < Esz / 32) {                                              \
            load_stage(sb + ((s + 1) & 1) * STAGE_B, Ah, Al, Bh, Bl,         \
                       m0, n0, (s + 1) * 32, tid);                           \
            CP_COMMIT();                                                     \
        }                                                                    \
        mma_stage(acc, sb + (s & 1) * STAGE_B, wm0, wn0, lane);              \
    }

// ---------------------------------------------------------------------------
// Kernel 1: qkv GEMM; epilogue writes pre-split bf16 Q/K/V (Q scaled 0.125)
// ---------------------------------------------------------------------------
__global__ __launch_bounds__(256, 2) void gemm_qkv(const float* __restrict__ bias) {
    GEMM_MAINLOOP(sXh, sXl, sWqh, sWql)

    const int g2 = lane >> 2, t2 = lane & 3;
#pragma unroll
    for (int i = 0; i < 4; i++) {
#pragma unroll
        for (int j = 0; j < 4; j++) {
            const int r0 = m0 + wm0 + i * 16 + g2;
            const int c0 = n0 + wn0 + j * 8 + t2 * 2;
            const int part = c0 >> 10, e = c0 & 1023;
            const int hh = e >> 6, d = e & 63;
            __nv_bfloat16 *dh, *dl;
            if (part == 0)      { dh = bQh; dl = bQl; }
            else if (part == 1) { dh = bKh; dl = bKl; }
            else                { dh = bVh; dl = bVl; }
            const float sc = (part == 0) ? 0.125f : 1.f;
            const float bb0 = bias[c0], bb1 = bias[c0 + 1];
            {
                const int b = r0 >> 11, sq = r0 & 2047;
                const int off = (((b << 4) + hh) * Ssz + sq) * HDd + d;
                uint32_t hi, lo;
                split2((acc[i][j][0] + bb0) * sc, (acc[i][j][1] + bb1) * sc, hi, lo);
                *(uint32_t*)(dh + off) = hi;
                *(uint32_t*)(dl + off) = lo;
            }
            {
                const int r1 = r0 + 8;
                const int b = r1 >> 11, sq = r1 & 2047;
                const int off = (((b << 4) + hh) * Ssz + sq) * HDd + d;
                uint32_t hi, lo;
                split2((acc[i][j][2] + bb0) * sc, (acc[i][j][3] + bb1) * sc, hi, lo);
                *(uint32_t*)(dh + off) = hi;
                *(uint32_t*)(dl + off) = lo;
            }
        }
    }
}

// ---------------------------------------------------------------------------
// Kernel 3: proj GEMM -> d_out
// ---------------------------------------------------------------------------
__global__ __launch_bounds__(256, 2) void gemm_proj(const float* __restrict__ bias,
                                                    float* __restrict__ out) {
    GEMM_MAINLOOP(sOh, sOl, sWph, sWpl)

    const int g2 = lane >> 2, t2 = lane & 3;
#pragma unroll
    for (int i = 0; i < 4; i++) {
#pragma unroll
        for (int j = 0; j < 4; j++) {
            const int r0 = m0 + wm0 + i * 16 + g2;
            const int c0 = n0 + wn0 + j * 8 + t2 * 2;
            const float b0 = bias[c0], b1 = bias[c0 + 1];
            float2 v0 = make_float2(acc[i][j][0] + b0, acc[i][j][1] + b1);
            float2 v1 = make_float2(acc[i][j][2] + b0, acc[i][j][3] + b1);
            *(float2*)(out + r0 * Esz + c0) = v0;
            *(float2*)(out + (r0 + 8) * Esz + c0) = v1;
        }
    }
}

// ---------------------------------------------------------------------------
// Pre-split kernels (X, weights)
// ---------------------------------------------------------------------------
__global__ __launch_bounds__(256) void split_plain(const float4* __restrict__ src,
                                                   uint2* __restrict__ h2,
                                                   uint2* __restrict__ l2) {
    const int i = blockIdx.x * 256 + threadIdx.x;
    const float4 v = src[i];
    uint32_t h0, l0, h1, l1;
    split2(v.x, v.y, h0, l0);
    split2(v.z, v.w, h1, l1);
    h2[i] = make_uint2(h0, h1);
    l2[i] = make_uint2(l0, l1);
}

__global__ __launch_bounds__(256) void split_w_tr(const float* __restrict__ W,
                                                  __nv_bfloat16* __restrict__ Th,
                                                  __nv_bfloat16* __restrict__ Tl,
                                                  int N) {
    __shared__ float t[32][33];
    const int k0 = blockIdx.y * 32, n0 = blockIdx.x * 32;
    const int tx = threadIdx.x & 31, ty = threadIdx.x >> 5;
#pragma unroll
    for (int r = ty; r < 32; r += 8)
        t[r][tx] = W[(k0 + r) * N + n0 + tx];
    __syncthreads();
#pragma unroll
    for (int r = ty; r < 32; r += 8) {
        const float v = t[tx][r];
        __nv_bfloat16 h = __float2bfloat16_rn(v);
        __nv_bfloat16 l = __float2bfloat16_rn(v - __bfloat162float(h));
        Th[(n0 + r) * Esz + k0 + tx] = h;
        Tl[(n0 + r) * Esz + k0 + tx] = l;
    }
}

// ---------------------------------------------------------------------------
// Kernel 2: tensor-core causal flash attention (round-7 proven geometry).
// grid = (32 q-tiles, 32 bh), 128 threads. Heavy q-tiles launched first.
// ---------------------------------------------------------------------------
#define AT_PITCH 144
#define AT_TILE (64 * AT_PITCH)              // 9216
#define AT_STAGE0 (2 * AT_TILE)              // Q hi/lo before stages
#define AT_STAGE_B (4 * AT_TILE)             // 36864
#define AT_SMEM (AT_STAGE0 + 2 * AT_STAGE_B) // 92160

__device__ __forceinline__ void at_load_kv(uint32_t st, int base, int kv0, int tid) {
#pragma unroll
    for (int gq = 0; gq < 4; gq++) {
        const int idx = gq * 128 + tid;          // 0..511
        const int row = idx >> 3, ch = idx & 7;
        const uint32_t d = st + row * AT_PITCH + ch * 16;
        const int off = base + (kv0 + row) * HDd + ch * 8;
        cp16(d, bKh + off);
        cp16(d + AT_TILE, bKl + off);
        cp16(d + 2 * AT_TILE, bVh + off);
        cp16(d + 3 * AT_TILE, bVl + off);
    }
}

__global__ __launch_bounds__(128, 2) void attn_tc() {
    extern __shared__ char dsm[];
    const uint32_t sb = smem_u32(dsm);
    const int tid = threadIdx.x, wid = tid >> 5, lane = tid & 31;
    const int bh = blockIdx.y;
    const int q0 = (gridDim.x - 1 - blockIdx.x) * 64;  // heavy tiles first
    const int wq0 = wid * 16;
    const int g = lane >> 2, t = lane & 3;
    const int base = bh * Ssz * HDd;

    // async: Q tile hi/lo
#pragma unroll
    for (int gq = 0; gq < 4; gq++) {
        const int idx = gq * 128 + tid;
        const int row = idx >> 3, ch = idx & 7;
        const uint32_t d = sb + row * AT_PITCH + ch * 16;
        const int off = base + (q0 + row) * HDd + ch * 8;
        cp16(d, bQh + off);
        cp16(d + AT_TILE, bQl + off);
    }
    at_load_kv(sb + AT_STAGE0, base, 0, tid);
    CP_COMMIT();

    const int T = q0 / 64 + 1;

    float oacc[8][4];
#pragma unroll
    for (int j = 0; j < 8; j++)
#pragma unroll
        for (int r = 0; r < 4; r++) oacc[j][r] = 0.f;
    float m_a = -1e30f, m_b = -1e30f, l_a = 0.f, l_b = 0.f;
    uint32_t qh[4][4], ql[4][4];

    const int laneRowB = (lane >> 4) * 8 + (lane & 7);
    const int chB = (lane >> 3) & 1;

    for (int tt = 0; tt < T; tt++) {
        if (tt + 1 < T) {
            at_load_kv(sb + AT_STAGE0 + ((tt + 1) & 1) * AT_STAGE_B,
                       base, (tt + 1) * 64, tid);
            CP_COMMIT();
            CP_WAIT(1);
        } else {
            CP_WAIT(0);
        }
        __syncthreads();

        if (tt == 0) {
#pragma unroll
            for (int ks = 0; ks < 4; ks++) {
                const uint32_t ra = sb + (wq0 + (lane & 15)) * AT_PITCH +
                                    (ks * 2 + (lane >> 4)) * 16;
                ldm4(qh[ks], ra);
                ldm4(ql[ks], ra + AT_TILE);
            }
        }

        const uint32_t st = sb + AT_STAGE0 + (tt & 1) * AT_STAGE_B;

        // S = Q K^T (bf16x3)
        float sacc[8][4];
#pragma unroll
        for (int j = 0; j < 8; j++)
#pragma unroll
            for (int r = 0; r < 4; r++) sacc[j][r] = 0.f;

#pragma unroll
        for (int jp = 0; jp < 4; jp++) {
#pragma unroll
            for (int ks = 0; ks < 4; ks++) {
                const uint32_t rb = st + (jp * 16 + laneRowB) * AT_PITCH +
                                    (ks * 2 + chB) * 16;
                uint32_t kh4[4], kl4[4];
                ldm4(kh4, rb);
                ldm4(kl4, rb + AT_TILE);
                mma16(sacc[jp * 2], qh[ks], &kh4[0]);
                mma16(sacc[jp * 2], qh[ks], &kl4[0]);
                mma16(sacc[jp * 2], ql[ks], &kh4[0]);
                mma16(sacc[jp * 2 + 1], qh[ks], &kh4[2]);
                mma16(sacc[jp * 2 + 1], qh[ks], &kl4[2]);
                mma16(sacc[jp * 2 + 1], ql[ks], &kh4[2]);
            }
        }

        const int rowa = q0 + wq0 + g;
        const int rowb = rowa + 8;

        // causal mask (diagonal tile only)
        if (tt == T - 1) {
            const int kvb = tt * 64;
#pragma unroll
            for (int j = 0; j < 8; j++) {
                const int c0 = kvb + j * 8 + t * 2;
                if (c0 > rowa) sacc[j][0] = -1e30f;
                if (c0 + 1 > rowa) sacc[j][1] = -1e30f;
                if (c0 > rowb) sacc[j][2] = -1e30f;
                if (c0 + 1 > rowb) sacc[j][3] = -1e30f;
            }
        }

        // online softmax
        float mxa = -1e30f, mxb = -1e30f;
#pragma unroll
        for (int j = 0; j < 8; j++) {
            mxa = fmaxf(mxa, fmaxf(sacc[j][0], sacc[j][1]));
            mxb = fmaxf(mxb, fmaxf(sacc[j][2], sacc[j][3]));
        }
        mxa = fmaxf(mxa, __shfl_xor_sync(0xffffffffu, mxa, 1));
        mxa = fmaxf(mxa, __shfl_xor_sync(0xffffffffu, mxa, 2));
        mxb = fmaxf(mxb, __shfl_xor_sync(0xffffffffu, mxb, 1));
        mxb = fmaxf(mxb, __shfl_xor_sync(0xffffffffu, mxb, 2));
        const float mna = fmaxf(m_a, mxa), mnb = fmaxf(m_b, mxb);
        const float ca = __expf(m_a - mna), cb = __expf(m_b - mnb);
        m_a = mna;
        m_b = mnb;

        float ra = 0.f, rb = 0.f;
        uint32_t ph[4][4], pl[4][4];
#pragma unroll
        for (int j = 0; j < 8; j++) {
            const float p0 = __expf(sacc[j][0] - mna);
            const float p1 = __expf(sacc[j][1] - mna);
            const float p2 = __expf(sacc[j][2] - mnb);
            const float p3 = __expf(sacc[j][3] - mnb);
            ra += p0 + p1;
            rb += p2 + p3;
            uint32_t h01, l01, h23, l23;
            split2(p0, p1, h01, l01);
            split2(p2, p3, h23, l23);
            const int ks = j >> 1, half = (j & 1) * 2;
            ph[ks][half] = h01;
            ph[ks][half + 1] = h23;
            pl[ks][half] = l01;
            pl[ks][half + 1] = l23;
        }
        ra += __shfl_xor_sync(0xffffffffu, ra, 1);
        ra += __shfl_xor_sync(0xffffffffu, ra, 2);
        rb += __shfl_xor_sync(0xffffffffu, rb, 1);
        rb += __shfl_xor_sync(0xffffffffu, rb, 2);
        l_a = l_a * ca + ra;
        l_b = l_b * cb + rb;

#pragma unroll
        for (int j = 0; j < 8; j++) {
            oacc[j][0] *= ca;
            oacc[j][1] *= ca;
            oacc[j][2] *= cb;
            oacc[j][3] *= cb;
        }

        // O += P V (bf16x3), V via trans-ldmatrix
        const uint32_t vbase = st + 2 * AT_TILE;
#pragma unroll
        for (int ks = 0; ks < 4; ks++) {
#pragma unroll
            for (int jp = 0; jp < 4; jp++) {
                const uint32_t va = vbase + (ks * 16 + (lane & 15)) * AT_PITCH +
                                    (jp * 16 + (lane >> 4) * 8) * 2;
                uint32_t vh4[4], vl4[4];
                ldm4t(vh4, va);
                ldm4t(vl4, va + AT_TILE);
                mma16(oacc[jp * 2], ph[ks], &vh4[0]);
                mma16(oacc[jp * 2], ph[ks], &vl4[0]);
                mma16(oacc[jp * 2], pl[ks], &vh4[0]);
                mma16(oacc[jp * 2 + 1], ph[ks], &vh4[2]);
                mma16(oacc[jp * 2 + 1], ph[ks], &vl4[2]);
                mma16(oacc[jp * 2 + 1], pl[ks], &vh4[2]);
            }
        }
        __syncthreads();
    }

    // normalize + write merged-head pre-split output
    const float ia = 1.f / l_a, ib = 1.f / l_b;
    const int b = bh >> 4, h = bh & 15;
    const int rowa = q0 + wq0 + g;
    const int moa = (b * Ssz + rowa) * Esz + h * HDd;
    const int mob = (b * Ssz + rowa + 8) * Esz + h * HDd;
#pragma unroll
    for (int j = 0; j < 8; j++) {
        const int d = j * 8 + t * 2;
        uint32_t h01, l01, h23, l23;
        split2(oacc[j][0] * ia, oacc[j][1] * ia, h01, l01);
        split2(oacc[j][2] * ib, oacc[j][3] * ib, h23, l23);
        *(uint32_t*)(sOh + moa + d) = h01;
        *(uint32_t*)(sOl + moa + d) = l01;
        *(uint32_t*)(sOh + mob + d) = h23;
        *(uint32_t*)(sOl + mob + d) = l23;
    }
}

// ---------------------------------------------------------------------------
extern "C" void kernel_launch(void* const* d_in, const int* in_sizes, int n_in,
                              void* d_out, int out_size) {
    const float* x = (const float*)d_in[0];
    const float* w_qkv = (const float*)d_in[1];
    const float* b_qkv = (const float*)d_in[2];
    const float* w_proj = (const float*)d_in[3];
    const float* b_proj = (const float*)d_in[4];
    float* out = (float*)d_out;

    static bool attr_done = false;
    if (!attr_done) {
        cudaFuncSetAttribute(gemm_qkv, cudaFuncAttributeMaxDynamicSharedMemorySize, SMEM_DYN);
        cudaFuncSetAttribute(gemm_proj, cudaFuncAttributeMaxDynamicSharedMemorySize, SMEM_DYN);
        cudaFuncSetAttribute(attn_tc, cudaFuncAttributeMaxDynamicSharedMemorySize, AT_SMEM);
        attr_done = true;
    }

    __nv_bfloat16 *pXh, *pXl, *pWqh, *pWql, *pWph, *pWpl;
    cudaGetSymbolAddress((void**)&pXh, sXh);
    cudaGetSymbolAddress((void**)&pXl, sXl);
    cudaGetSymbolAddress((void**)&pWqh, sWqh);
    cudaGetSymbolAddress((void**)&pWql, sWql);
    cudaGetSymbolAddress((void**)&pWph, sWph);
    cudaGetSymbolAddress((void**)&pWpl, sWpl);

    split_plain<<<Msz * Esz / 4 / 256, 256>>>((const float4*)x, (uint2*)pXh, (uint2*)pXl);
    split_w_tr<<<dim3(NQKV / 32, Esz / 32), 256>>>(w_qkv, pWqh, pWql, NQKV);
    split_w_tr<<<dim3(Esz / 32, Esz / 32), 256>>>(w_proj, pWph, pWpl, Esz);
    gemm_qkv<<<dim3(NQKV / 128, Msz / 128), 256, SMEM_DYN>>>(b_qkv);
    attn_tc<<<dim3(Ssz / 64, Bsz * Hsz), 128, AT_SMEM>>>();
    gemm_proj<<<dim3(Esz / 128, Msz / 128), 256, SMEM_DYN>>>(b_proj, out);
}